// round 12
// baseline (speedup 1.0000x reference)
#include <cuda_runtime.h>
#include <cuda_fp16.h>
#include <cstdint>

#define DIM 1024
#define NO  256
#define NR  512
#define BMAX 128
#define BM  128
#define BN  128
#define BK  64            // fp16 k per stage = 4 x k16 steps
#define STAGES 3
#define A_BYTES (BM*BK*2)                 // 16 KB
#define B_BYTES (BK*BN*2)                 // 16 KB
#define STAGE_BYTES (A_BYTES + B_BYTES)   // 32 KB
#define SMEM_BYTES (STAGES*STAGE_BYTES)   // 96 KB -> 2 CTAs/SM

// fp16 converted operands (static scratch; no allocation)
__device__ __half g_obj_h [BMAX*NO*DIM];
__device__ __half g_attr_h[BMAX*NO*DIM];
__device__ __half g_rela_h[BMAX*NR*DIM];
__device__ __half g_Wa_h  [2048*DIM];
__device__ __half g_Wr_h  [3072*DIM];

// ---------- helpers ----------
__device__ __forceinline__ void cpa16(uint32_t s, const void* g){
    asm volatile("cp.async.cg.shared.global [%0], [%1], 16;" :: "r"(s), "l"(g));
}
__device__ __forceinline__ void cpcommit(){ asm volatile("cp.async.commit_group;"); }
template<int N> __device__ __forceinline__ void cpwait(){
    asm volatile("cp.async.wait_group %0;" :: "n"(N));
}
__device__ __forceinline__ void ldmA(uint32_t* r, uint32_t a){
    asm volatile("ldmatrix.sync.aligned.m8n8.x4.shared.b16 {%0,%1,%2,%3}, [%4];"
        : "=r"(r[0]), "=r"(r[1]), "=r"(r[2]), "=r"(r[3]) : "r"(a));
}
__device__ __forceinline__ void ldmBT(uint32_t* r, uint32_t a){
    asm volatile("ldmatrix.sync.aligned.m8n8.x4.trans.shared.b16 {%0,%1,%2,%3}, [%4];"
        : "=r"(r[0]), "=r"(r[1]), "=r"(r[2]), "=r"(r[3]) : "r"(a));
}
__device__ __forceinline__ void mma16(float* c, const uint32_t* a, const uint32_t* b){
    asm volatile("mma.sync.aligned.m16n8k16.row.col.f32.f16.f16.f32 "
        "{%0,%1,%2,%3}, {%4,%5,%6,%7}, {%8,%9}, {%0,%1,%2,%3};"
        : "+f"(c[0]), "+f"(c[1]), "+f"(c[2]), "+f"(c[3])
        : "r"(a[0]), "r"(a[1]), "r"(a[2]), "r"(a[3]), "r"(b[0]), "r"(b[1]));
}

// ---------- consolidated fp32 -> fp16 prepass ----------
// One launch converts all 5 tensors. Each block owns 1024 contiguous float4
// chunks; every segment length is a multiple of 1024 chunks, so a block never
// straddles segments. Segment 0 (obj) also writes the fp32 passthrough copy.
// 4 independent float4s per thread (MLP=4).
__global__ __launch_bounds__(256)
void f2h_all(const float4* __restrict__ obj,  uint2* __restrict__ objh,
             float4* __restrict__ objcpy,
             const float4* __restrict__ attr, uint2* __restrict__ attrh,
             const float4* __restrict__ rela, uint2* __restrict__ relah,
             const float4* __restrict__ Wa,   uint2* __restrict__ wah,
             const float4* __restrict__ Wr,   uint2* __restrict__ wrh,
             long e0, long e1, long e2, long e3)     // segment end prefix (blocks)
{
    const long blk = blockIdx.x;
    const float4* src; uint2* dst; long lb; bool docpy = false;
    if      (blk < e0) { src = obj;  dst = objh;  lb = blk;      docpy = true; }
    else if (blk < e1) { src = attr; dst = attrh; lb = blk - e0; }
    else if (blk < e2) { src = rela; dst = relah; lb = blk - e1; }
    else if (blk < e3) { src = Wa;   dst = wah;   lb = blk - e2; }
    else               { src = Wr;   dst = wrh;   lb = blk - e3; }

    const long base = lb * 1024 + threadIdx.x;
    #pragma unroll
    for (int k = 0; k < 4; k++) {
        const long i = base + k * 256;
        const float4 v = src[i];
        const __half2 h0 = __floats2half2_rn(v.x, v.y);
        const __half2 h1 = __floats2half2_rn(v.z, v.w);
        uint2 o;
        o.x = *(const uint32_t*)&h0;
        o.y = *(const uint32_t*)&h1;
        dst[i] = o;
        if (docpy) objcpy[i] = v;
    }
}

// ---------- fp16 mma.sync GEMM (round-9 structure, unchanged) ----------
// MODE 1: A = [obj | attr],         K=2048, residual=attr
// MODE 2: A = [obj[s]|rela|obj[o]], K=3072, residual=rela, *mask
// 256 threads = 8 warps (4x2), warp tile 32x64, CTA tile 128x128.
template<int MODE>
__global__ __launch_bounds__(256, 2)
void gnn_gemm(const __half* __restrict__ objh, const __half* __restrict__ xh,
              const float* __restrict__ xres,
              const int* __restrict__ edges, const float* __restrict__ masks,
              const __half* __restrict__ Wh, const float* __restrict__ bias,
              float* __restrict__ out)
{
    constexpr int K  = (MODE==1) ? 2048 : 3072;
    constexpr int KT = K / BK;

    extern __shared__ char smem[];
    __shared__ int sS[BM], sO[BM];
    __shared__ int sI32;

    const uint32_t smem_base = (uint32_t)__cvta_generic_to_shared(smem);
    const int tid  = threadIdx.x;
    const int nblk = blockIdx.x;
    const long row0 = (long)blockIdx.y * BM;
    const long n0   = (long)nblk * BN;

    if (MODE == 2) {
        if (tid < 32) {
            // sniff edges layout: int64 -> every odd 32-bit word is a zero high-word
            int w = edges[2*tid + 1];
            unsigned bal = __ballot_sync(0xffffffffu, w != 0);
            if (tid == 0) sI32 = (bal != 0);
        }
        __syncthreads();
        if (tid < BM) {
            long r  = row0 + tid;
            int  bb = (int)(r >> 9);         // r / NR
            int  s, o;
            if (sI32) { s = edges[2*r]; o = edges[2*r + 1]; }
            else      { s = edges[4*r]; o = edges[4*r + 2]; }
            sS[tid] = bb*NO + s;
            sO[tid] = bb*NO + o;
        }
        __syncthreads();
    }

    auto load_stage = [&](int j){
        const int st = j % STAGES;
        const uint32_t a_s = smem_base + st*STAGE_BYTES;
        const uint32_t b_s = a_s + A_BYTES;
        const int k0  = j * BK;              // fp16 element offset in concat-K
        const int seg = k0 >> 10;            // 64 | 1024 -> never straddles
        const int kin = k0 & 1023;
        // A: 128 rows x 128B (64 fp16); 1024 x 16B chunks; 4 per thread
        #pragma unroll
        for (int i = 0; i < 4; i++) {
            const int chunk = tid + i*256;
            const int r = chunk >> 3;        // row 0..127
            const int c = chunk & 7;         // 16B chunk in row
            const __half* src;
            if (MODE == 1) {
                src = (seg == 0 ? objh : xh) + (row0 + r)*DIM + kin + c*8;
            } else {
                if (seg == 0)      src = objh + (long)sS[r]*DIM + kin + c*8;
                else if (seg == 1) src = xh   + (row0 + r)*DIM  + kin + c*8;
                else               src = objh + (long)sO[r]*DIM + kin + c*8;
            }
            cpa16(a_s + (uint32_t)(r*128 + ((c ^ r) & 7)*16), src);
        }
        // B: 64 k-rows x 256B (128 fp16); 1024 x 16B chunks; 4 per thread
        #pragma unroll
        for (int i = 0; i < 4; i++) {
            const int chunk = tid + i*256;
            const int r = chunk >> 4;        // k row 0..63
            const int c = chunk & 15;        // 16B chunk in row
            const __half* src = Wh + (long)(k0 + r)*DIM + n0 + c*8;
            cpa16(b_s + (uint32_t)(r*256 + (c & 8)*16 + ((c ^ r) & 7)*16), src);
        }
        cpcommit();
    };

    float acc[2][8][4];
    #pragma unroll
    for (int a = 0; a < 2; a++)
        #pragma unroll
        for (int b = 0; b < 8; b++)
            #pragma unroll
            for (int c = 0; c < 4; c++) acc[a][b][c] = 0.f;

    const int wid = tid >> 5, lane = tid & 31;
    const int warpM = wid >> 1, warpN = wid & 1;   // 4x2 warps, warp tile 32x64
    const int grp = lane >> 2, qd = lane & 3;

    // ldmatrix lane-address components
    const int l8  = lane & 7;
    const int lm8 = (lane & 8) ? 8 : 0;            // second 8x8 block (rows +8)
    const int l16 = (lane >> 4) & 1;               // third/fourth block (cols +8)

    load_stage(0);
    load_stage(1);

    for (int kt = 0; kt < KT; kt++) {
        cpwait<STAGES-2>();
        __syncthreads();

        const int st = kt % STAGES;
        const uint32_t a_s = smem_base + st*STAGE_BYTES;
        const uint32_t b_s = a_s + A_BYTES;

        #pragma unroll
        for (int ks = 0; ks < BK/16; ks++) {
            // A frags: 2 m16 tiles
            uint32_t af[2][4];
            #pragma unroll
            for (int mt = 0; mt < 2; mt++) {
                const int mr = warpM*32 + mt*16 + l8 + lm8;
                const int ch = ks*2 + l16;                      // 16B chunk (k8 step)
                ldmA(af[mt], a_s + (uint32_t)(mr*128 + ((ch ^ mr) & 7)*16));
            }
            // B frags: 4 n16 groups (-> 8 n8 tiles), transposed from k-major W
            uint32_t bf[8][2];
            #pragma unroll
            for (int ng = 0; ng < 4; ng++) {
                const int kr = ks*16 + l8 + lm8;                // stored k row
                const int c  = warpN*8 + ng*2 + l16;            // 16B chunk (n8 group)
                uint32_t t[4];
                ldmBT(t, b_s + (uint32_t)(kr*256 + (c & 8)*16 + ((c ^ kr) & 7)*16));
                bf[2*ng+0][0] = t[0]; bf[2*ng+0][1] = t[1];
                bf[2*ng+1][0] = t[2]; bf[2*ng+1][1] = t[3];
            }
            #pragma unroll
            for (int mt = 0; mt < 2; mt++)
                #pragma unroll
                for (int nt = 0; nt < 8; nt++)
                    mma16(acc[mt][nt], af[mt], bf[nt]);
        }

        const int jn = kt + STAGES - 1;
        if (jn < KT) load_stage(jn);
    }

    // Epilogue: +bias, relu, +residual(fp32), (mask), store
    #pragma unroll
    for (int mt = 0; mt < 2; mt++) {
        const long r0 = row0 + warpM*32 + mt*16 + grp;
        #pragma unroll
        for (int nt = 0; nt < 8; nt++) {
            const long c  = n0 + warpN*64 + nt*8 + 2*qd;
            const float2 bs = *(const float2*)(bias + c);
            #pragma unroll
            for (int h = 0; h < 2; h++) {
                const long rr = r0 + 8*h;
                const float2 res = *(const float2*)(xres + rr*DIM + c);
                float v0 = acc[mt][nt][2*h + 0] + bs.x;
                float v1 = acc[mt][nt][2*h + 1] + bs.y;
                v0 = fmaxf(v0, 0.f) + res.x;
                v1 = fmaxf(v1, 0.f) + res.y;
                if (MODE == 2) { const float m = masks[rr]; v0 *= m; v1 *= m; }
                *(float2*)(out + rr*DIM + c) = make_float2(v0, v1);
            }
        }
    }
}

extern "C" void kernel_launch(void* const* d_in, const int* in_sizes, int n_in,
                              void* d_out, int out_size)
{
    const float* obj   = (const float*)d_in[0];
    const float* attr  = (const float*)d_in[1];
    const float* rela  = (const float*)d_in[2];
    const int*   edges = (const int*)  d_in[3];
    const float* masks = (const float*)d_in[4];
    const float* Wa    = (const float*)d_in[5];
    const float* ba    = (const float*)d_in[6];
    const float* Wr    = (const float*)d_in[7];
    const float* br    = (const float*)d_in[8];

    const int    B     = in_sizes[0] / (NO * DIM);
    const size_t objN  = (size_t)B * NO * DIM;
    const size_t relaN = (size_t)B * NR * DIM;
    float* out = (float*)d_out;

    __half *objh, *attrh, *relah, *wah, *wrh;
    cudaGetSymbolAddress((void**)&objh,  g_obj_h);
    cudaGetSymbolAddress((void**)&attrh, g_attr_h);
    cudaGetSymbolAddress((void**)&relah, g_rela_h);
    cudaGetSymbolAddress((void**)&wah,   g_Wa_h);
    cudaGetSymbolAddress((void**)&wrh,   g_Wr_h);

    // consolidated prepass: one launch, 1024 float4-chunks per block
    const long objB  = (long)(objN  / 4) / 1024;     // blocks per segment
    const long relaB = (long)(relaN / 4) / 1024;
    const long waB   = (long)(2048*DIM / 4) / 1024;
    const long wrB   = (long)(3072*DIM / 4) / 1024;
    const long e0 = objB, e1 = e0 + objB, e2 = e1 + relaB, e3 = e2 + waB;
    const long total = e3 + wrB;
    f2h_all<<<(int)total, 256>>>(
        (const float4*)obj,  (uint2*)objh, (float4*)out,
        (const float4*)attr, (uint2*)attrh,
        (const float4*)rela, (uint2*)relah,
        (const float4*)Wa,   (uint2*)wah,
        (const float4*)Wr,   (uint2*)wrh,
        e0, e1, e2, e3);

    cudaFuncSetAttribute(gnn_gemm<1>, cudaFuncAttributeMaxDynamicSharedMemorySize, SMEM_BYTES);
    cudaFuncSetAttribute(gnn_gemm<2>, cudaFuncAttributeMaxDynamicSharedMemorySize, SMEM_BYTES);

    const int M1 = B * NO;   // 32768
    const int M2 = B * NR;   // 65536
    gnn_gemm<1><<<dim3(DIM/BN, M1/BM), 256, SMEM_BYTES>>>(
        objh, attrh, attr, nullptr, nullptr, wah, ba, out + objN);
    gnn_gemm<2><<<dim3(DIM/BN, M2/BM), 256, SMEM_BYTES>>>(
        objh, relah, rela, edges, masks, wrh, br, out + 2*objN);
}

// round 13
// speedup vs baseline: 1.6553x; 1.6553x over previous
#include <cuda_runtime.h>
#include <cuda_fp16.h>
#include <cstdint>

#define DIM 1024
#define NO  256
#define NR  512
#define BMAX 128
#define BM  128
#define BN  128
#define BK  64            // fp16 k per stage = 4 x k16 steps
#define STAGES 3
#define A_BYTES (BM*BK*2)                 // 16 KB
#define B_BYTES (BK*BN*2)                 // 16 KB
#define STAGE_BYTES (A_BYTES + B_BYTES)   // 32 KB
#define SMEM_BYTES (STAGES*STAGE_BYTES)   // 96 KB -> 2 CTAs/SM

// fp16 converted operands + fp32 T scratch (static; no allocation)
__device__ __half g_obj_h [BMAX*NO*DIM];
__device__ __half g_attr_h[BMAX*NO*DIM];
__device__ __half g_rela_h[BMAX*NR*DIM];
__device__ __half g_Wa_h  [2048*DIM];
__device__ __half g_Wr_h  [3072*DIM];
__device__ float  g_T     [(size_t)BMAX*NO*2048];   // [32768][2048]: [obj@Wr1 | obj@Wr3]

// ---------- helpers ----------
__device__ __forceinline__ void cpa16(uint32_t s, const void* g){
    asm volatile("cp.async.cg.shared.global [%0], [%1], 16;" :: "r"(s), "l"(g));
}
__device__ __forceinline__ void cpcommit(){ asm volatile("cp.async.commit_group;"); }
template<int N> __device__ __forceinline__ void cpwait(){
    asm volatile("cp.async.wait_group %0;" :: "n"(N));
}
__device__ __forceinline__ void ldmA(uint32_t* r, uint32_t a){
    asm volatile("ldmatrix.sync.aligned.m8n8.x4.shared.b16 {%0,%1,%2,%3}, [%4];"
        : "=r"(r[0]), "=r"(r[1]), "=r"(r[2]), "=r"(r[3]) : "r"(a));
}
__device__ __forceinline__ void ldmBT(uint32_t* r, uint32_t a){
    asm volatile("ldmatrix.sync.aligned.m8n8.x4.trans.shared.b16 {%0,%1,%2,%3}, [%4];"
        : "=r"(r[0]), "=r"(r[1]), "=r"(r[2]), "=r"(r[3]) : "r"(a));
}
__device__ __forceinline__ void mma16(float* c, const uint32_t* a, const uint32_t* b){
    asm volatile("mma.sync.aligned.m16n8k16.row.col.f32.f16.f16.f32 "
        "{%0,%1,%2,%3}, {%4,%5,%6,%7}, {%8,%9}, {%0,%1,%2,%3};"
        : "+f"(c[0]), "+f"(c[1]), "+f"(c[2]), "+f"(c[3])
        : "r"(a[0]), "r"(a[1]), "r"(a[2]), "r"(a[3]), "r"(b[0]), "r"(b[1]));
}

// ---------- fp32 -> fp16 conversion prepass (round-9 version, unchanged) ----------
__global__ void f2h(const float4* __restrict__ src, uint2* __restrict__ dst, long n4){
    const long i = (long)blockIdx.x * blockDim.x + threadIdx.x;
    if (i >= n4) return;
    const float4 v = src[i];
    const __half2 h0 = __floats2half2_rn(v.x, v.y);
    const __half2 h1 = __floats2half2_rn(v.z, v.w);
    uint2 o;
    o.x = *(const uint32_t*)&h0;
    o.y = *(const uint32_t*)&h1;
    dst[i] = o;
}

// ---------- fp16 mma.sync GEMM (round-9 loop structure) ----------
// MODE 1: A = [obj | attr] (K=2048), epi: relu(+bias)+attr           -> out
// MODE 3: A = obj          (K=1024), epi: plain fp32 store           -> T (row stride 2048)
// MODE 4: A = rela         (K=1024), epi: relu(+bias+T1[s]+T2[o])+rela, *mask -> out
// 256 threads = 8 warps (4x2), warp tile 32x64, CTA tile 128x128.
template<int MODE>
__global__ __launch_bounds__(256, 2)
void gnn_gemm(const __half* __restrict__ objh, const __half* __restrict__ xh,
              const float* __restrict__ xres,
              const int* __restrict__ edges, const float* __restrict__ masks,
              const __half* __restrict__ Wh, const float* __restrict__ bias,
              const float* __restrict__ T,
              float* __restrict__ out)
{
    constexpr int K  = (MODE==1) ? 2048 : 1024;
    constexpr int KT = K / BK;
    constexpr int RS = (MODE==3) ? 2048 : DIM;     // out row stride

    extern __shared__ char smem[];
    __shared__ int sS[BM], sO[BM];
    __shared__ int sI32;

    const uint32_t smem_base = (uint32_t)__cvta_generic_to_shared(smem);
    const int tid  = threadIdx.x;
    const int nblk = blockIdx.x;
    const long row0 = (long)blockIdx.y * BM;
    const long n0   = (long)nblk * BN;

    if (MODE == 4) {
        if (tid < 32) {
            // sniff edges layout: int64 -> every odd 32-bit word is a zero high-word
            int w = edges[2*tid + 1];
            unsigned bal = __ballot_sync(0xffffffffu, w != 0);
            if (tid == 0) sI32 = (bal != 0);
        }
        __syncthreads();
        if (tid < BM) {
            long r  = row0 + tid;
            int  bb = (int)(r >> 9);         // r / NR
            int  s, o;
            if (sI32) { s = edges[2*r]; o = edges[2*r + 1]; }
            else      { s = edges[4*r]; o = edges[4*r + 2]; }
            sS[tid] = bb*NO + s;
            sO[tid] = bb*NO + o;
        }
        __syncthreads();
    }

    auto load_stage = [&](int j){
        const int st = j % STAGES;
        const uint32_t a_s = smem_base + st*STAGE_BYTES;
        const uint32_t b_s = a_s + A_BYTES;
        const int k0  = j * BK;              // fp16 element offset in (concat-)K
        // A: 128 rows x 128B (64 fp16); 1024 x 16B chunks; 4 per thread
        #pragma unroll
        for (int i = 0; i < 4; i++) {
            const int chunk = tid + i*256;
            const int r = chunk >> 3;        // row 0..127
            const int c = chunk & 7;         // 16B chunk in row
            const __half* src;
            if (MODE == 1) {
                const int seg = k0 >> 10;    // 64 | 1024 -> never straddles
                const int kin = k0 & 1023;
                src = (seg == 0 ? objh : xh) + (row0 + r)*DIM + kin + c*8;
            } else if (MODE == 3) {
                src = objh + (row0 + r)*DIM + k0 + c*8;
            } else {
                src = xh   + (row0 + r)*DIM + k0 + c*8;
            }
            cpa16(a_s + (uint32_t)(r*128 + ((c ^ r) & 7)*16), src);
        }
        // B: 64 k-rows x 256B (128 fp16); 1024 x 16B chunks; 4 per thread
        #pragma unroll
        for (int i = 0; i < 4; i++) {
            const int chunk = tid + i*256;
            const int r = chunk >> 4;        // k row 0..63
            const int c = chunk & 15;        // 16B chunk in row
            const __half* src = Wh + (long)(k0 + r)*DIM + n0 + c*8;
            cpa16(b_s + (uint32_t)(r*256 + (c & 8)*16 + ((c ^ r) & 7)*16), src);
        }
        cpcommit();
    };

    float acc[2][8][4];
    #pragma unroll
    for (int a = 0; a < 2; a++)
        #pragma unroll
        for (int b = 0; b < 8; b++)
            #pragma unroll
            for (int c = 0; c < 4; c++) acc[a][b][c] = 0.f;

    const int wid = tid >> 5, lane = tid & 31;
    const int warpM = wid >> 1, warpN = wid & 1;   // 4x2 warps, warp tile 32x64
    const int grp = lane >> 2, qd = lane & 3;

    // ldmatrix lane-address components
    const int l8  = lane & 7;
    const int lm8 = (lane & 8) ? 8 : 0;            // second 8x8 block (rows +8)
    const int l16 = (lane >> 4) & 1;               // third/fourth block (cols +8)

    load_stage(0);
    load_stage(1);

    for (int kt = 0; kt < KT; kt++) {
        cpwait<STAGES-2>();
        __syncthreads();

        const int st = kt % STAGES;
        const uint32_t a_s = smem_base + st*STAGE_BYTES;
        const uint32_t b_s = a_s + A_BYTES;

        #pragma unroll
        for (int ks = 0; ks < BK/16; ks++) {
            // A frags: 2 m16 tiles
            uint32_t af[2][4];
            #pragma unroll
            for (int mt = 0; mt < 2; mt++) {
                const int mr = warpM*32 + mt*16 + l8 + lm8;
                const int ch = ks*2 + l16;                      // 16B chunk (k8 step)
                ldmA(af[mt], a_s + (uint32_t)(mr*128 + ((ch ^ mr) & 7)*16));
            }
            // B frags: 4 n16 groups (-> 8 n8 tiles), transposed from k-major W
            uint32_t bf[8][2];
            #pragma unroll
            for (int ng = 0; ng < 4; ng++) {
                const int kr = ks*16 + l8 + lm8;                // stored k row
                const int c  = warpN*8 + ng*2 + l16;            // 16B chunk (n8 group)
                uint32_t t[4];
                ldmBT(t, b_s + (uint32_t)(kr*256 + (c & 8)*16 + ((c ^ kr) & 7)*16));
                bf[2*ng+0][0] = t[0]; bf[2*ng+0][1] = t[1];
                bf[2*ng+1][0] = t[2]; bf[2*ng+1][1] = t[3];
            }
            #pragma unroll
            for (int mt = 0; mt < 2; mt++)
                #pragma unroll
                for (int nt = 0; nt < 8; nt++)
                    mma16(acc[mt][nt], af[mt], bf[nt]);
        }

        const int jn = kt + STAGES - 1;
        if (jn < KT) load_stage(jn);
    }

    // Epilogue
    #pragma unroll
    for (int mt = 0; mt < 2; mt++) {
        const int  lr0 = warpM*32 + mt*16 + grp;   // local row 0..127
        const long r0  = row0 + lr0;
        #pragma unroll
        for (int nt = 0; nt < 8; nt++) {
            const long c = n0 + warpN*64 + nt*8 + 2*qd;
            if (MODE == 3) {
                #pragma unroll
                for (int h = 0; h < 2; h++) {
                    const long rr = r0 + 8*h;
                    *(float2*)(out + rr*RS + c) =
                        make_float2(acc[mt][nt][2*h + 0], acc[mt][nt][2*h + 1]);
                }
            } else {
                const float2 bs = *(const float2*)(bias + c);
                #pragma unroll
                for (int h = 0; h < 2; h++) {
                    const long rr = r0 + 8*h;
                    const float2 res = *(const float2*)(xres + rr*DIM + c);
                    float v0 = acc[mt][nt][2*h + 0] + bs.x;
                    float v1 = acc[mt][nt][2*h + 1] + bs.y;
                    if (MODE == 4) {
                        const int lr = lr0 + 8*h;
                        const float2 t1 = *(const float2*)(T + (long)sS[lr]*2048 + c);
                        const float2 t2 = *(const float2*)(T + (long)sO[lr]*2048 + 1024 + c);
                        v0 += t1.x + t2.x;
                        v1 += t1.y + t2.y;
                    }
                    v0 = fmaxf(v0, 0.f) + res.x;
                    v1 = fmaxf(v1, 0.f) + res.y;
                    if (MODE == 4) { const float m = masks[rr]; v0 *= m; v1 *= m; }
                    *(float2*)(out + rr*DIM + c) = make_float2(v0, v1);
                }
            }
        }
    }
}

extern "C" void kernel_launch(void* const* d_in, const int* in_sizes, int n_in,
                              void* d_out, int out_size)
{
    const float* obj   = (const float*)d_in[0];
    const float* attr  = (const float*)d_in[1];
    const float* rela  = (const float*)d_in[2];
    const int*   edges = (const int*)  d_in[3];
    const float* masks = (const float*)d_in[4];
    const float* Wa    = (const float*)d_in[5];
    const float* ba    = (const float*)d_in[6];
    const float* Wr    = (const float*)d_in[7];
    const float* br    = (const float*)d_in[8];

    const int    B     = in_sizes[0] / (NO * DIM);
    const size_t objN  = (size_t)B * NO * DIM;
    const size_t relaN = (size_t)B * NR * DIM;
    float* out = (float*)d_out;

    __half *objh, *attrh, *relah, *wah, *wrh;
    float* Tp;
    cudaGetSymbolAddress((void**)&objh,  g_obj_h);
    cudaGetSymbolAddress((void**)&attrh, g_attr_h);
    cudaGetSymbolAddress((void**)&relah, g_rela_h);
    cudaGetSymbolAddress((void**)&wah,   g_Wa_h);
    cudaGetSymbolAddress((void**)&wrh,   g_Wr_h);
    cudaGetSymbolAddress((void**)&Tp,    g_T);

    // fp32 -> fp16 prepass (round-9 launches, unchanged)
    auto conv = [&](const float* s, __half* d, size_t n){
        const long n4 = (long)(n / 4);
        const int grid = (int)((n4 + 255) / 256);
        f2h<<<grid, 256>>>((const float4*)s, (uint2*)d, n4);
    };
    conv(obj,  objh,  objN);
    conv(attr, attrh, objN);
    conv(rela, relah, relaN);
    conv(Wa,   wah,   (size_t)2048*DIM);
    conv(Wr,   wrh,   (size_t)3072*DIM);

    // output layout: [new_obj | new_attr | new_rela]
    cudaMemcpyAsync(out, obj, objN * sizeof(float), cudaMemcpyDeviceToDevice);

    cudaFuncSetAttribute(gnn_gemm<1>, cudaFuncAttributeMaxDynamicSharedMemorySize, SMEM_BYTES);
    cudaFuncSetAttribute(gnn_gemm<3>, cudaFuncAttributeMaxDynamicSharedMemorySize, SMEM_BYTES);
    cudaFuncSetAttribute(gnn_gemm<4>, cudaFuncAttributeMaxDynamicSharedMemorySize, SMEM_BYTES);

    const int M1 = B * NO;   // 32768
    const int M2 = B * NR;   // 65536

    // T1 = obj @ Wr1 -> T[:, 0:1024];  T2 = obj @ Wr3 -> T[:, 1024:2048]
    gnn_gemm<3><<<dim3(DIM/BN, M1/BM), 256, SMEM_BYTES>>>(
        objh, nullptr, nullptr, nullptr, nullptr, wrh,              nullptr, nullptr, Tp);
    gnn_gemm<3><<<dim3(DIM/BN, M1/BM), 256, SMEM_BYTES>>>(
        objh, nullptr, nullptr, nullptr, nullptr, wrh + 2048*DIM,   nullptr, nullptr, Tp + 1024);

    // new_attr = relu([obj|attr] @ Wa + ba) + attr
    gnn_gemm<1><<<dim3(DIM/BN, M1/BM), 256, SMEM_BYTES>>>(
        objh, attrh, attr, nullptr, nullptr, wah, ba, nullptr, out + objN);

    // new_rela = (relu(rela @ Wr2 + T1[s] + T2[o] + br) + rela) * mask
    gnn_gemm<4><<<dim3(DIM/BN, M2/BM), 256, SMEM_BYTES>>>(
        objh, relah, rela, edges, masks, wrh + 1024*DIM, br, Tp, out + 2*objN);
}

// round 17
// speedup vs baseline: 1.7163x; 1.0368x over previous
#include <cuda_runtime.h>
#include <cuda_fp16.h>
#include <cstdint>

#define DIM 1024
#define NO  256
#define NR  512
#define BMAX 128
#define BM  128
#define BN  128
#define BK  64            // fp16 k per stage = 4 x k16 steps
#define STAGES 3
#define A_BYTES (BM*BK*2)                 // 16 KB
#define B_BYTES (BK*BN*2)                 // 16 KB
#define STAGE_BYTES (A_BYTES + B_BYTES)   // 32 KB
#define SMEM_BYTES (STAGES*STAGE_BYTES)   // 96 KB -> 2 CTAs/SM

// fp16 converted operands + fp16 T scratch (static; no allocation)
__device__ __half g_obj_h [BMAX*NO*DIM];
__device__ __half g_attr_h[BMAX*NO*DIM];
__device__ __half g_rela_h[BMAX*NR*DIM];
__device__ __half g_Wa_h  [2048*DIM];
__device__ __half g_Wr_h  [3072*DIM];
__device__ __half g_T     [(size_t)BMAX*NO*2048];   // [32768][2048]: [obj@Wr1 | obj@Wr3]

// ---------- helpers ----------
__device__ __forceinline__ void cpa16(uint32_t s, const void* g){
    asm volatile("cp.async.cg.shared.global [%0], [%1], 16;" :: "r"(s), "l"(g));
}
__device__ __forceinline__ void cpcommit(){ asm volatile("cp.async.commit_group;"); }
template<int N> __device__ __forceinline__ void cpwait(){
    asm volatile("cp.async.wait_group %0;" :: "n"(N));
}
__device__ __forceinline__ void ldmA(uint32_t* r, uint32_t a){
    asm volatile("ldmatrix.sync.aligned.m8n8.x4.shared.b16 {%0,%1,%2,%3}, [%4];"
        : "=r"(r[0]), "=r"(r[1]), "=r"(r[2]), "=r"(r[3]) : "r"(a));
}
__device__ __forceinline__ void ldmBT(uint32_t* r, uint32_t a){
    asm volatile("ldmatrix.sync.aligned.m8n8.x4.trans.shared.b16 {%0,%1,%2,%3}, [%4];"
        : "=r"(r[0]), "=r"(r[1]), "=r"(r[2]), "=r"(r[3]) : "r"(a));
}
__device__ __forceinline__ void mma16(float* c, const uint32_t* a, const uint32_t* b){
    asm volatile("mma.sync.aligned.m16n8k16.row.col.f32.f16.f16.f32 "
        "{%0,%1,%2,%3}, {%4,%5,%6,%7}, {%8,%9}, {%0,%1,%2,%3};"
        : "+f"(c[0]), "+f"(c[1]), "+f"(c[2]), "+f"(c[3])
        : "r"(a[0]), "r"(a[1]), "r"(a[2]), "r"(a[3]), "r"(b[0]), "r"(b[1]));
}

// ---------- fp32 -> fp16 conversion prepass (round-9 version, unchanged) ----------
__global__ void f2h(const float4* __restrict__ src, uint2* __restrict__ dst, long n4){
    const long i = (long)blockIdx.x * blockDim.x + threadIdx.x;
    if (i >= n4) return;
    const float4 v = src[i];
    const __half2 h0 = __floats2half2_rn(v.x, v.y);
    const __half2 h1 = __floats2half2_rn(v.z, v.w);
    uint2 o;
    o.x = *(const uint32_t*)&h0;
    o.y = *(const uint32_t*)&h1;
    dst[i] = o;
}

// ---------- fp16 mma.sync GEMM (round-9 loop structure) ----------
// MODE 1: A = [obj | attr] (K=2048), epi: relu(+bias)+attr                  -> out (fp32)
// MODE 3: A = obj (K=1024), N=2048 merged (Wh for n<1024, Wh2 for n>=1024),
//         epi: fp16 store                                                    -> T
// MODE 4: A = rela (K=1024), epi: relu(+bias+T1[s]+T2[o])+rela, *mask       -> out (fp32)
// 256 threads = 8 warps (4x2), warp tile 32x64, CTA tile 128x128.
template<int MODE>
__global__ __launch_bounds__(256, 2)
void gnn_gemm(const __half* __restrict__ objh, const __half* __restrict__ xh,
              const float* __restrict__ xres,
              const int* __restrict__ edges, const float* __restrict__ masks,
              const __half* __restrict__ Wh, const __half* __restrict__ Wh2,
              const float* __restrict__ bias,
              const __half* __restrict__ T,
              float* __restrict__ out)
{
    constexpr int K  = (MODE==1) ? 2048 : 1024;
    constexpr int KT = K / BK;

    extern __shared__ char smem[];
    __shared__ int sS[BM], sO[BM];
    __shared__ int sI32;

    const uint32_t smem_base = (uint32_t)__cvta_generic_to_shared(smem);
    const int tid  = threadIdx.x;
    const int nblk = blockIdx.x;
    const long row0 = (long)blockIdx.y * BM;
    const long n0   = (long)nblk * BN;

    // merged mode-3: pick weight segment by output-column block (uniform per CTA)
    const __half* Wsel = (MODE == 3 && n0 >= 1024) ? Wh2 : Wh;
    const long    nW   = (MODE == 3) ? (n0 & 1023) : n0;

    if (MODE == 4) {
        if (tid < 32) {
            // sniff edges layout: int64 -> every odd 32-bit word is a zero high-word
            int w = edges[2*tid + 1];
            unsigned bal = __ballot_sync(0xffffffffu, w != 0);
            if (tid == 0) sI32 = (bal != 0);
        }
        __syncthreads();
        if (tid < BM) {
            long r  = row0 + tid;
            int  bb = (int)(r >> 9);         // r / NR
            int  s, o;
            if (sI32) { s = edges[2*r]; o = edges[2*r + 1]; }
            else      { s = edges[4*r]; o = edges[4*r + 2]; }
            sS[tid] = bb*NO + s;
            sO[tid] = bb*NO + o;
        }
        __syncthreads();
    }

    auto load_stage = [&](int j){
        const int st = j % STAGES;
        const uint32_t a_s = smem_base + st*STAGE_BYTES;
        const uint32_t b_s = a_s + A_BYTES;
        const int k0  = j * BK;              // fp16 element offset in (concat-)K
        // A: 128 rows x 128B (64 fp16); 1024 x 16B chunks; 4 per thread
        #pragma unroll
        for (int i = 0; i < 4; i++) {
            const int chunk = tid + i*256;
            const int r = chunk >> 3;        // row 0..127
            const int c = chunk & 7;         // 16B chunk in row
            const __half* src;
            if (MODE == 1) {
                const int seg = k0 >> 10;    // 64 | 1024 -> never straddles
                const int kin = k0 & 1023;
                src = (seg == 0 ? objh : xh) + (row0 + r)*DIM + kin + c*8;
            } else if (MODE == 3) {
                src = objh + (row0 + r)*DIM + k0 + c*8;
            } else {
                src = xh   + (row0 + r)*DIM + k0 + c*8;
            }
            cpa16(a_s + (uint32_t)(r*128 + ((c ^ r) & 7)*16), src);
        }
        // B: 64 k-rows x 256B (128 fp16); 1024 x 16B chunks; 4 per thread
        #pragma unroll
        for (int i = 0; i < 4; i++) {
            const int chunk = tid + i*256;
            const int r = chunk >> 4;        // k row 0..63
            const int c = chunk & 15;        // 16B chunk in row
            const __half* src = Wsel + (long)(k0 + r)*DIM + nW + c*8;
            cpa16(b_s + (uint32_t)(r*256 + (c & 8)*16 + ((c ^ r) & 7)*16), src);
        }
        cpcommit();
    };

    float acc[2][8][4];
    #pragma unroll
    for (int a = 0; a < 2; a++)
        #pragma unroll
        for (int b = 0; b < 8; b++)
            #pragma unroll
            for (int c = 0; c < 4; c++) acc[a][b][c] = 0.f;

    const int wid = tid >> 5, lane = tid & 31;
    const int warpM = wid >> 1, warpN = wid & 1;   // 4x2 warps, warp tile 32x64
    const int grp = lane >> 2, qd = lane & 3;

    // ldmatrix lane-address components
    const int l8  = lane & 7;
    const int lm8 = (lane & 8) ? 8 : 0;            // second 8x8 block (rows +8)
    const int l16 = (lane >> 4) & 1;               // third/fourth block (cols +8)

    load_stage(0);
    load_stage(1);

    for (int kt = 0; kt < KT; kt++) {
        cpwait<STAGES-2>();
        __syncthreads();

        const int st = kt % STAGES;
        const uint32_t a_s = smem_base + st*STAGE_BYTES;
        const uint32_t b_s = a_s + A_BYTES;

        #pragma unroll
        for (int ks = 0; ks < BK/16; ks++) {
            // A frags: 2 m16 tiles
            uint32_t af[2][4];
            #pragma unroll
            for (int mt = 0; mt < 2; mt++) {
                const int mr = warpM*32 + mt*16 + l8 + lm8;
                const int ch = ks*2 + l16;                      // 16B chunk (k8 step)
                ldmA(af[mt], a_s + (uint32_t)(mr*128 + ((ch ^ mr) & 7)*16));
            }
            // B frags: 4 n16 groups (-> 8 n8 tiles), transposed from k-major W
            uint32_t bf[8][2];
            #pragma unroll
            for (int ng = 0; ng < 4; ng++) {
                const int kr = ks*16 + l8 + lm8;                // stored k row
                const int c  = warpN*8 + ng*2 + l16;            // 16B chunk (n8 group)
                uint32_t t[4];
                ldmBT(t, b_s + (uint32_t)(kr*256 + (c & 8)*16 + ((c ^ kr) & 7)*16));
                bf[2*ng+0][0] = t[0]; bf[2*ng+0][1] = t[1];
                bf[2*ng+1][0] = t[2]; bf[2*ng+1][1] = t[3];
            }
            #pragma unroll
            for (int mt = 0; mt < 2; mt++)
                #pragma unroll
                for (int nt = 0; nt < 8; nt++)
                    mma16(acc[mt][nt], af[mt], bf[nt]);
        }

        const int jn = kt + STAGES - 1;
        if (jn < KT) load_stage(jn);
    }

    // Epilogue
    #pragma unroll
    for (int mt = 0; mt < 2; mt++) {
        const int  lr0 = warpM*32 + mt*16 + grp;   // local row 0..127
        const long r0  = row0 + lr0;
        #pragma unroll
        for (int nt = 0; nt < 8; nt++) {
            const long c = n0 + warpN*64 + nt*8 + 2*qd;
            if (MODE == 3) {
                __half* Th = (__half*)out;
                #pragma unroll
                for (int h = 0; h < 2; h++) {
                    const long rr = r0 + 8*h;
                    const __half2 hv = __floats2half2_rn(acc[mt][nt][2*h + 0],
                                                         acc[mt][nt][2*h + 1]);
                    *(__half2*)(Th + rr*2048 + c) = hv;
                }
            } else {
                const float2 bs = *(const float2*)(bias + c);
                #pragma unroll
                for (int h = 0; h < 2; h++) {
                    const long rr = r0 + 8*h;
                    const float2 res = *(const float2*)(xres + rr*DIM + c);
                    float v0 = acc[mt][nt][2*h + 0] + bs.x;
                    float v1 = acc[mt][nt][2*h + 1] + bs.y;
                    if (MODE == 4) {
                        const int lr = lr0 + 8*h;
                        const __half2 t1 = *(const __half2*)(T + (long)sS[lr]*2048 + c);
                        const __half2 t2 = *(const __half2*)(T + (long)sO[lr]*2048 + 1024 + c);
                        const float2 t1f = __half22float2(t1);
                        const float2 t2f = __half22float2(t2);
                        v0 += t1f.x + t2f.x;
                        v1 += t1f.y + t2f.y;
                    }
                    v0 = fmaxf(v0, 0.f) + res.x;
                    v1 = fmaxf(v1, 0.f) + res.y;
                    if (MODE == 4) { const float m = masks[rr]; v0 *= m; v1 *= m; }
                    *(float2*)(out + rr*DIM + c) = make_float2(v0, v1);
                }
            }
        }
    }
}

extern "C" void kernel_launch(void* const* d_in, const int* in_sizes, int n_in,
                              void* d_out, int out_size)
{
    const float* obj   = (const float*)d_in[0];
    const float* attr  = (const float*)d_in[1];
    const float* rela  = (const float*)d_in[2];
    const int*   edges = (const int*)  d_in[3];
    const float* masks = (const float*)d_in[4];
    const float* Wa    = (const float*)d_in[5];
    const float* ba    = (const float*)d_in[6];
    const float* Wr    = (const float*)d_in[7];
    const float* br    = (const float*)d_in[8];

    const int    B     = in_sizes[0] / (NO * DIM);
    const size_t objN  = (size_t)B * NO * DIM;
    const size_t relaN = (size_t)B * NR * DIM;
    float* out = (float*)d_out;

    __half *objh, *attrh, *relah, *wah, *wrh, *Tp;
    cudaGetSymbolAddress((void**)&objh,  g_obj_h);
    cudaGetSymbolAddress((void**)&attrh, g_attr_h);
    cudaGetSymbolAddress((void**)&relah, g_rela_h);
    cudaGetSymbolAddress((void**)&wah,   g_Wa_h);
    cudaGetSymbolAddress((void**)&wrh,   g_Wr_h);
    cudaGetSymbolAddress((void**)&Tp,    g_T);

    // fp32 -> fp16 prepass (round-9 launches, unchanged)
    auto conv = [&](const float* s, __half* d, size_t n){
        const long n4 = (long)(n / 4);
        const int grid = (int)((n4 + 255) / 256);
        f2h<<<grid, 256>>>((const float4*)s, (uint2*)d, n4);
    };
    conv(obj,  objh,  objN);
    conv(attr, attrh, objN);
    conv(rela, relah, relaN);
    conv(Wa,   wah,   (size_t)2048*DIM);
    conv(Wr,   wrh,   (size_t)3072*DIM);

    // output layout: [new_obj | new_attr | new_rela]
    cudaMemcpyAsync(out, obj, objN * sizeof(float), cudaMemcpyDeviceToDevice);

    cudaFuncSetAttribute(gnn_gemm<1>, cudaFuncAttributeMaxDynamicSharedMemorySize, SMEM_BYTES);
    cudaFuncSetAttribute(gnn_gemm<3>, cudaFuncAttributeMaxDynamicSharedMemorySize, SMEM_BYTES);
    cudaFuncSetAttribute(gnn_gemm<4>, cudaFuncAttributeMaxDynamicSharedMemorySize, SMEM_BYTES);

    const int M1 = B * NO;   // 32768
    const int M2 = B * NR;   // 65536

    // T = obj @ [Wr1 | Wr3] -> fp16 T[:, 0:2048]  (single merged launch, N=2048)
    gnn_gemm<3><<<dim3(2048/BN, M1/BM), 256, SMEM_BYTES>>>(
        objh, nullptr, nullptr, nullptr, nullptr,
        wrh, wrh + (size_t)2048*DIM, nullptr, nullptr, (float*)Tp);

    // new_attr = relu([obj|attr] @ Wa + ba) + attr
    gnn_gemm<1><<<dim3(DIM/BN, M1/BM), 256, SMEM_BYTES>>>(
        objh, attrh, attr, nullptr, nullptr,
        wah, nullptr, ba, nullptr, out + objN);

    // new_rela = (relu(rela @ Wr2 + T1[s] + T2[o] + br) + rela) * mask
    gnn_gemm<4><<<dim3(DIM/BN, M2/BM), 256, SMEM_BYTES>>>(
        objh, relah, rela, edges, masks,
        wrh + (size_t)1024*DIM, nullptr, br, Tp, out + 2*objN);
}